// round 10
// baseline (speedup 1.0000x reference)
#include <cuda_runtime.h>
#include <cuda_bf16.h>

// Problem constants (fixed by setup_inputs): B=4, H=16, N=4096, d=128, Br=Bc=128.
#define BH_      64
#define NSEQ_    4096
#define DIM_     128
#define BR_      128
#define BC_      128
#define QSTRIDE  132   // floats per Q smem row (pad 4 -> conflict-free A-frag loads)
#define KSTRIDE  132   // floats per K smem row
#define VSTRIDE  136   // floats per V smem row (pad 8 -> conflict-free B-frag loads)
#define NTHREADS 256

__device__ __forceinline__ unsigned tf32_rna(float x) {
    unsigned u;
    asm("cvt.rna.tf32.f32 %0, %1;" : "=r"(u) : "f"(x));
    return u;
}

__device__ __forceinline__ void mma_tf32(float& d0, float& d1, float& d2, float& d3,
                                         unsigned a0, unsigned a1, unsigned a2, unsigned a3,
                                         unsigned b0, unsigned b1) {
    asm("mma.sync.aligned.m16n8k8.row.col.f32.tf32.tf32.f32 "
        "{%0,%1,%2,%3}, {%4,%5,%6,%7}, {%8,%9}, {%0,%1,%2,%3};\n"
        : "+f"(d0), "+f"(d1), "+f"(d2), "+f"(d3)
        : "r"(a0), "r"(a1), "r"(a2), "r"(a3), "r"(b0), "r"(b1));
}

__global__ __launch_bounds__(NTHREADS, 1)
void fa_tf32_kernel(const float* __restrict__ Q, const float* __restrict__ K,
                    const float* __restrict__ V, float* __restrict__ Out) {
    extern __shared__ float smem[];
    float* Qs  = smem;                    // BR_ x QSTRIDE
    float* Ksm = Qs  + BR_ * QSTRIDE;     // BC_ x KSTRIDE
    float* Vsm = Ksm + BC_ * KSTRIDE;     // BC_ x VSTRIDE

    const int tid  = threadIdx.x;
    const int warp = tid >> 5;
    const int lane = tid & 31;
    const int g    = lane >> 2;   // groupID (row within fragment)
    const int q4   = lane & 3;    // threadID_in_group

    const int bh = blockIdx.y;
    const int qt = blockIdx.x;
    const size_t base = (size_t)bh * NSEQ_ * DIM_;
    const float* Qg = Q + base + (size_t)qt * BR_ * DIM_;
    const float* Kg = K + base;
    const float* Vg = V + base;

    // fold (1/sqrt(d)) * log2(e) into Q so scores are directly in exp2 domain
    const float qscale = 1.4426950408889634f * 0.08838834764831845f;

    // ---- load Q tile once (scaled + tf32-rounded), resident whole kernel ----
    for (int i = tid; i < BR_ * DIM_ / 4; i += NTHREADS) {
        int r = i >> 5;
        int c = (i & 31) << 2;
        float4 qv = *reinterpret_cast<const float4*>(Qg + (size_t)r * DIM_ + c);
        float4 o;
        o.x = __uint_as_float(tf32_rna(qv.x * qscale));
        o.y = __uint_as_float(tf32_rna(qv.y * qscale));
        o.z = __uint_as_float(tf32_rna(qv.z * qscale));
        o.w = __uint_as_float(tf32_rna(qv.w * qscale));
        *reinterpret_cast<float4*>(Qs + r * QSTRIDE + c) = o;
    }

    // ---- accumulators: 16 n-tiles x 4 regs each for S and for O ----
    float Sa[16][4];
    float Oa[16][4];
    #pragma unroll
    for (int n = 0; n < 16; n++) {
        Oa[n][0] = 0.f; Oa[n][1] = 0.f; Oa[n][2] = 0.f; Oa[n][3] = 0.f;
    }
    float m0 = -INFINITY, m1 = -INFINITY;   // running row max (rows g, g+8 of warp block)
    float l0 = 0.f, l1 = 0.f;               // running row sum

    const int qoff0 = (warp * 16 + g) * QSTRIDE;       // A-frag row g
    const int qoff1 = (warp * 16 + g + 8) * QSTRIDE;   // A-frag row g+8

    const unsigned FULL = 0xffffffffu;

    for (int t = 0; t < NSEQ_ / BC_; ++t) {
        __syncthreads();  // previous iteration's K/V reads done before overwrite
        const float* Kt = Kg + (size_t)t * BC_ * DIM_;
        const float* Vt = Vg + (size_t)t * BC_ * DIM_;
        for (int i = tid; i < BC_ * DIM_ / 4; i += NTHREADS) {
            int r = i >> 5;
            int c = (i & 31) << 2;
            float4 kv = *reinterpret_cast<const float4*>(Kt + (size_t)r * DIM_ + c);
            float4 vv = *reinterpret_cast<const float4*>(Vt + (size_t)r * DIM_ + c);
            float4 ko, vo;
            ko.x = __uint_as_float(tf32_rna(kv.x));
            ko.y = __uint_as_float(tf32_rna(kv.y));
            ko.z = __uint_as_float(tf32_rna(kv.z));
            ko.w = __uint_as_float(tf32_rna(kv.w));
            vo.x = __uint_as_float(tf32_rna(vv.x));
            vo.y = __uint_as_float(tf32_rna(vv.y));
            vo.z = __uint_as_float(tf32_rna(vv.z));
            vo.w = __uint_as_float(tf32_rna(vv.w));
            *reinterpret_cast<float4*>(Ksm + r * KSTRIDE + c) = ko;
            *reinterpret_cast<float4*>(Vsm + r * VSTRIDE + c) = vo;
        }
        __syncthreads();

        // ================= S = Q @ K^T (16x128 per warp) =================
        #pragma unroll
        for (int n = 0; n < 16; n++) {
            Sa[n][0] = 0.f; Sa[n][1] = 0.f; Sa[n][2] = 0.f; Sa[n][3] = 0.f;
        }
        #pragma unroll 4
        for (int k = 0; k < 16; k++) {
            const int kc = k * 8 + q4;
            unsigned a0 = __float_as_uint(Qs[qoff0 + kc]);
            unsigned a1 = __float_as_uint(Qs[qoff1 + kc]);
            unsigned a2 = __float_as_uint(Qs[qoff0 + kc + 4]);
            unsigned a3 = __float_as_uint(Qs[qoff1 + kc + 4]);
            #pragma unroll
            for (int n = 0; n < 16; n++) {
                const float* kb = Ksm + (n * 8 + g) * KSTRIDE + kc;
                unsigned b0 = __float_as_uint(kb[0]);
                unsigned b1 = __float_as_uint(kb[4]);
                mma_tf32(Sa[n][0], Sa[n][1], Sa[n][2], Sa[n][3], a0, a1, a2, a3, b0, b1);
            }
        }

        // ================= online softmax (exp2 domain) =================
        float mx0 = Sa[0][0], mx1 = Sa[0][2];
        #pragma unroll
        for (int n = 0; n < 16; n++) {
            mx0 = fmaxf(mx0, fmaxf(Sa[n][0], Sa[n][1]));
            mx1 = fmaxf(mx1, fmaxf(Sa[n][2], Sa[n][3]));
        }
        mx0 = fmaxf(mx0, __shfl_xor_sync(FULL, mx0, 1));
        mx0 = fmaxf(mx0, __shfl_xor_sync(FULL, mx0, 2));
        mx1 = fmaxf(mx1, __shfl_xor_sync(FULL, mx1, 1));
        mx1 = fmaxf(mx1, __shfl_xor_sync(FULL, mx1, 2));

        float mn0 = fmaxf(m0, mx0), mn1 = fmaxf(m1, mx1);
        float al0 = exp2f(m0 - mn0);   // exp2f(-inf)=0 on first tile
        float al1 = exp2f(m1 - mn1);
        m0 = mn0; m1 = mn1;

        float rs0 = 0.f, rs1 = 0.f;
        #pragma unroll
        for (int n = 0; n < 16; n++) {
            float p0 = exp2f(Sa[n][0] - mn0);
            float p1 = exp2f(Sa[n][1] - mn0);
            float p2 = exp2f(Sa[n][2] - mn1);
            float p3 = exp2f(Sa[n][3] - mn1);
            rs0 += p0 + p1;
            rs1 += p2 + p3;
            Sa[n][0] = __uint_as_float(tf32_rna(p0));
            Sa[n][1] = __uint_as_float(tf32_rna(p1));
            Sa[n][2] = __uint_as_float(tf32_rna(p2));
            Sa[n][3] = __uint_as_float(tf32_rna(p3));
        }
        rs0 += __shfl_xor_sync(FULL, rs0, 1);
        rs0 += __shfl_xor_sync(FULL, rs0, 2);
        rs1 += __shfl_xor_sync(FULL, rs1, 1);
        rs1 += __shfl_xor_sync(FULL, rs1, 2);
        l0 = al0 * l0 + rs0;
        l1 = al1 * l1 + rs1;

        #pragma unroll
        for (int n = 0; n < 16; n++) {
            Oa[n][0] *= al0; Oa[n][1] *= al0;
            Oa[n][2] *= al1; Oa[n][3] *= al1;
        }

        // ================= O += P @ V =================
        const int s0 = (lane & ~3) | (q4 >> 1);  // quad lane holding cols {q4}
        const int s1 = s0 + 2;                   // quad lane holding cols {q4+4}
        const bool odd = (q4 & 1);
        #pragma unroll
        for (int kt = 0; kt < 16; kt++) {
            // C-frag (rows g,g+8 x cols 2q,2q+1) -> A-frag (cols q4, q4+4) via quad shuffles
            float c0 = Sa[kt][0], c1 = Sa[kt][1], c2 = Sa[kt][2], c3 = Sa[kt][3];
            float x0 = __shfl_sync(FULL, c0, s0);
            float x1 = __shfl_sync(FULL, c1, s0);
            float x2 = __shfl_sync(FULL, c2, s0);
            float x3 = __shfl_sync(FULL, c3, s0);
            float y0 = __shfl_sync(FULL, c0, s1);
            float y1 = __shfl_sync(FULL, c1, s1);
            float y2 = __shfl_sync(FULL, c2, s1);
            float y3 = __shfl_sync(FULL, c3, s1);
            unsigned pa0 = __float_as_uint(odd ? x1 : x0);  // row g,   col q4
            unsigned pa1 = __float_as_uint(odd ? x3 : x2);  // row g+8, col q4
            unsigned pa2 = __float_as_uint(odd ? y1 : y0);  // row g,   col q4+4
            unsigned pa3 = __float_as_uint(odd ? y3 : y2);  // row g+8, col q4+4
            const float* vb0 = Vsm + (kt * 8 + q4) * VSTRIDE + g;
            const float* vb1 = vb0 + 4 * VSTRIDE;
            #pragma unroll
            for (int n = 0; n < 16; n++) {
                unsigned b0 = __float_as_uint(vb0[n * 8]);
                unsigned b1 = __float_as_uint(vb1[n * 8]);
                mma_tf32(Oa[n][0], Oa[n][1], Oa[n][2], Oa[n][3], pa0, pa1, pa2, pa3, b0, b1);
            }
        }
    }

    // ================= epilogue: O / l =================
    const float inv0 = 1.0f / l0;
    const float inv1 = 1.0f / l1;
    float* Og = Out + base + (size_t)qt * BR_ * DIM_;
    const int r0 = warp * 16 + g;
    const int r1 = r0 + 8;
    #pragma unroll
    for (int n = 0; n < 16; n++) {
        float2 v0 = make_float2(Oa[n][0] * inv0, Oa[n][1] * inv0);
        float2 v1 = make_float2(Oa[n][2] * inv1, Oa[n][3] * inv1);
        *reinterpret_cast<float2*>(Og + (size_t)r0 * DIM_ + n * 8 + 2 * q4) = v0;
        *reinterpret_cast<float2*>(Og + (size_t)r1 * DIM_ + n * 8 + 2 * q4) = v1;
    }
}

extern "C" void kernel_launch(void* const* d_in, const int* in_sizes, int n_in,
                              void* d_out, int out_size) {
    const float* Q = (const float*)d_in[0];
    const float* K = (const float*)d_in[1];
    const float* V = (const float*)d_in[2];
    float* O = (float*)d_out;

    const size_t smem_bytes =
        (size_t)(BR_ * QSTRIDE + BC_ * KSTRIDE + BC_ * VSTRIDE) * sizeof(float); // 204800 B
    cudaFuncSetAttribute(fa_tf32_kernel, cudaFuncAttributeMaxDynamicSharedMemorySize,
                         (int)smem_bytes);

    dim3 grid(NSEQ_ / BR_, BH_);  // (32, 64): same-bh CTAs adjacent -> K/V L2 reuse
    fa_tf32_kernel<<<grid, NTHREADS, smem_bytes>>>(Q, K, V, O);
}

// round 11
// speedup vs baseline: 1.2378x; 1.2378x over previous
#include <cuda_runtime.h>
#include <cuda_bf16.h>

// Problem constants (fixed by setup_inputs): B=4, H=16, N=4096, d=128, Br=Bc=128.
#define BH_      64
#define NSEQ_    4096
#define DIM_     128
#define BR_      128
#define BC_      128
#define QSTRIDE  132   // floats per Q smem row (pad 4 -> conflict-free A-frag loads)
#define KSTRIDE  132   // floats per K smem row
#define VSTRIDE  136   // floats per V smem row (pad 8 -> conflict-free B-frag loads)
#define NTHREADS 256

__device__ __forceinline__ unsigned tf32_rna(float x) {
    unsigned u;
    asm("cvt.rna.tf32.f32 %0, %1;" : "=r"(u) : "f"(x));
    return u;
}

__device__ __forceinline__ void mma_tf32(float& d0, float& d1, float& d2, float& d3,
                                         unsigned a0, unsigned a1, unsigned a2, unsigned a3,
                                         unsigned b0, unsigned b1) {
    asm("mma.sync.aligned.m16n8k8.row.col.f32.tf32.tf32.f32 "
        "{%0,%1,%2,%3}, {%4,%5,%6,%7}, {%8,%9}, {%0,%1,%2,%3};\n"
        : "+f"(d0), "+f"(d1), "+f"(d2), "+f"(d3)
        : "r"(a0), "r"(a1), "r"(a2), "r"(a3), "r"(b0), "r"(b1));
}

// async-copy one 128x128 f32 tile (row-major, DIM_ cols) into padded smem.
// 16B per cp.async; 4096 float4s spread over NTHREADS threads.
__device__ __forceinline__ void cpasync_tile(float* dst, const float* __restrict__ src,
                                             int stride, int tid) {
    unsigned dbase = (unsigned)__cvta_generic_to_shared(dst);
    #pragma unroll
    for (int i = 0; i < (BC_ * DIM_ / 4) / NTHREADS; i++) {
        int idx = i * NTHREADS + tid;
        int r = idx >> 5;
        int c = (idx & 31) << 2;
        unsigned d = dbase + (unsigned)(r * stride + c) * 4u;
        const float* s = src + (size_t)r * DIM_ + c;
        asm volatile("cp.async.cg.shared.global [%0], [%1], 16;\n" :: "r"(d), "l"(s));
    }
}

__device__ __forceinline__ void cp_commit() {
    asm volatile("cp.async.commit_group;\n" ::: "memory");
}
__device__ __forceinline__ void cp_wait1() {
    asm volatile("cp.async.wait_group 1;\n" ::: "memory");
}

__global__ __launch_bounds__(NTHREADS, 1)
void fa_tf32_kernel(const float* __restrict__ Q, const float* __restrict__ K,
                    const float* __restrict__ V, float* __restrict__ Out) {
    extern __shared__ float smem[];
    float* Qs  = smem;                    // BR_ x QSTRIDE
    float* Ksm = Qs  + BR_ * QSTRIDE;     // BC_ x KSTRIDE
    float* Vsm = Ksm + BC_ * KSTRIDE;     // BC_ x VSTRIDE

    const int tid  = threadIdx.x;
    const int warp = tid >> 5;
    const int lane = tid & 31;
    const int g    = lane >> 2;   // groupID (row within fragment)
    const int q4   = lane & 3;    // threadID_in_group

    const int bh = blockIdx.y;
    const int qt = blockIdx.x;
    const size_t base = (size_t)bh * NSEQ_ * DIM_;
    const float* Qg = Q + base + (size_t)qt * BR_ * DIM_;
    const float* Kg = K + base;
    const float* Vg = V + base;

    // ---- prologue: start K(0), V(0) async; load Q (scaled+rna) meanwhile ----
    cpasync_tile(Ksm, Kg, KSTRIDE, tid); cp_commit();   // group: K0
    cpasync_tile(Vsm, Vg, VSTRIDE, tid); cp_commit();   // group: V0

    // fold (1/sqrt(d)) * log2(e) into Q so scores are directly in exp2 domain
    const float qscale = 1.4426950408889634f * 0.08838834764831845f;
    for (int i = tid; i < BR_ * DIM_ / 4; i += NTHREADS) {
        int r = i >> 5;
        int c = (i & 31) << 2;
        float4 qv = *reinterpret_cast<const float4*>(Qg + (size_t)r * DIM_ + c);
        float4 o;
        o.x = __uint_as_float(tf32_rna(qv.x * qscale));
        o.y = __uint_as_float(tf32_rna(qv.y * qscale));
        o.z = __uint_as_float(tf32_rna(qv.z * qscale));
        o.w = __uint_as_float(tf32_rna(qv.w * qscale));
        *reinterpret_cast<float4*>(Qs + r * QSTRIDE + c) = o;
    }

    cp_wait1();        // K0 arrived (V0 may still be in flight)
    __syncthreads();   // loop invariant: Kbuf ready+visible, V(t) pending <=1 group

    // ---- accumulators: 16 n-tiles x 4 regs each for S and for O ----
    float Sa[16][4];
    float Oa[16][4];
    #pragma unroll
    for (int n = 0; n < 16; n++) {
        Oa[n][0] = 0.f; Oa[n][1] = 0.f; Oa[n][2] = 0.f; Oa[n][3] = 0.f;
    }
    float m0 = -INFINITY, m1 = -INFINITY;   // running row max (rows g, g+8 of warp block)
    float l0 = 0.f, l1 = 0.f;               // running row sum

    const int qoff0 = (warp * 16 + g) * QSTRIDE;       // A-frag row g
    const int qoff1 = (warp * 16 + g + 8) * QSTRIDE;   // A-frag row g+8

    const unsigned FULL = 0xffffffffu;

    #pragma unroll 1
    for (int t = 0; t < NSEQ_ / BC_; ++t) {
        // ================= S = Q @ K^T (16x128 per warp) =================
        #pragma unroll
        for (int n = 0; n < 16; n++) {
            Sa[n][0] = 0.f; Sa[n][1] = 0.f; Sa[n][2] = 0.f; Sa[n][3] = 0.f;
        }
        #pragma unroll 4
        for (int k = 0; k < 16; k++) {
            const int kc = k * 8 + q4;
            unsigned a0 = __float_as_uint(Qs[qoff0 + kc]);
            unsigned a1 = __float_as_uint(Qs[qoff1 + kc]);
            unsigned a2 = __float_as_uint(Qs[qoff0 + kc + 4]);
            unsigned a3 = __float_as_uint(Qs[qoff1 + kc + 4]);
            #pragma unroll
            for (int n = 0; n < 16; n++) {
                const float* kb = Ksm + (n * 8 + g) * KSTRIDE + kc;
                unsigned b0 = __float_as_uint(kb[0]);
                unsigned b1 = __float_as_uint(kb[4]);
                mma_tf32(Sa[n][0], Sa[n][1], Sa[n][2], Sa[n][3], a0, a1, a2, a3, b0, b1);
            }
        }

        __syncthreads();   // all warps finished reading Kbuf
        if (t + 1 < NSEQ_ / BC_)
            cpasync_tile(Ksm, Kg + (size_t)(t + 1) * BC_ * DIM_, KSTRIDE, tid);
        cp_commit();       // group: K(t+1) (possibly empty on last iter)
        cp_wait1();        // V(t) arrived (K(t+1) still in flight)
        __syncthreads();   // Vbuf visible to all warps

        // ================= online softmax (exp2 domain) =================
        float mx0 = Sa[0][0], mx1 = Sa[0][2];
        #pragma unroll
        for (int n = 0; n < 16; n++) {
            mx0 = fmaxf(mx0, fmaxf(Sa[n][0], Sa[n][1]));
            mx1 = fmaxf(mx1, fmaxf(Sa[n][2], Sa[n][3]));
        }
        mx0 = fmaxf(mx0, __shfl_xor_sync(FULL, mx0, 1));
        mx0 = fmaxf(mx0, __shfl_xor_sync(FULL, mx0, 2));
        mx1 = fmaxf(mx1, __shfl_xor_sync(FULL, mx1, 1));
        mx1 = fmaxf(mx1, __shfl_xor_sync(FULL, mx1, 2));

        float mn0 = fmaxf(m0, mx0), mn1 = fmaxf(m1, mx1);
        float al0 = exp2f(m0 - mn0);   // exp2f(-inf)=0 on first tile
        float al1 = exp2f(m1 - mn1);
        m0 = mn0; m1 = mn1;

        float rs0 = 0.f, rs1 = 0.f;
        #pragma unroll
        for (int n = 0; n < 16; n++) {
            float p0 = exp2f(Sa[n][0] - mn0);
            float p1 = exp2f(Sa[n][1] - mn0);
            float p2 = exp2f(Sa[n][2] - mn1);
            float p3 = exp2f(Sa[n][3] - mn1);
            rs0 += p0 + p1;
            rs1 += p2 + p3;
            Sa[n][0] = __uint_as_float(tf32_rna(p0));
            Sa[n][1] = __uint_as_float(tf32_rna(p1));
            Sa[n][2] = __uint_as_float(tf32_rna(p2));
            Sa[n][3] = __uint_as_float(tf32_rna(p3));
        }
        rs0 += __shfl_xor_sync(FULL, rs0, 1);
        rs0 += __shfl_xor_sync(FULL, rs0, 2);
        rs1 += __shfl_xor_sync(FULL, rs1, 1);
        rs1 += __shfl_xor_sync(FULL, rs1, 2);
        l0 = al0 * l0 + rs0;
        l1 = al1 * l1 + rs1;

        #pragma unroll
        for (int n = 0; n < 16; n++) {
            Oa[n][0] *= al0; Oa[n][1] *= al0;
            Oa[n][2] *= al1; Oa[n][3] *= al1;
        }

        // ================= O += P @ V (overlaps K(t+1) fetch) =================
        const int s0 = (lane & ~3) | (q4 >> 1);  // quad lane holding cols {q4}
        const int s1 = s0 + 2;                   // quad lane holding cols {q4+4}
        const bool odd = (q4 & 1);
        #pragma unroll
        for (int kt = 0; kt < 16; kt++) {
            // C-frag (rows g,g+8 x cols 2q,2q+1) -> A-frag (cols q4, q4+4) via quad shuffles
            float c0 = Sa[kt][0], c1 = Sa[kt][1], c2 = Sa[kt][2], c3 = Sa[kt][3];
            float x0 = __shfl_sync(FULL, c0, s0);
            float x1 = __shfl_sync(FULL, c1, s0);
            float x2 = __shfl_sync(FULL, c2, s0);
            float x3 = __shfl_sync(FULL, c3, s0);
            float y0 = __shfl_sync(FULL, c0, s1);
            float y1 = __shfl_sync(FULL, c1, s1);
            float y2 = __shfl_sync(FULL, c2, s1);
            float y3 = __shfl_sync(FULL, c3, s1);
            unsigned pa0 = __float_as_uint(odd ? x1 : x0);  // row g,   col q4
            unsigned pa1 = __float_as_uint(odd ? x3 : x2);  // row g+8, col q4
            unsigned pa2 = __float_as_uint(odd ? y1 : y0);  // row g,   col q4+4
            unsigned pa3 = __float_as_uint(odd ? y3 : y2);  // row g+8, col q4+4
            const float* vb0 = Vsm + (kt * 8 + q4) * VSTRIDE + g;
            const float* vb1 = vb0 + 4 * VSTRIDE;
            #pragma unroll
            for (int n = 0; n < 16; n++) {
                unsigned b0 = __float_as_uint(vb0[n * 8]);
                unsigned b1 = __float_as_uint(vb1[n * 8]);
                mma_tf32(Oa[n][0], Oa[n][1], Oa[n][2], Oa[n][3], pa0, pa1, pa2, pa3, b0, b1);
            }
        }

        __syncthreads();   // all warps finished reading Vbuf
        if (t + 1 < NSEQ_ / BC_)
            cpasync_tile(Vsm, Vg + (size_t)(t + 1) * BC_ * DIM_, VSTRIDE, tid);
        cp_commit();       // group: V(t+1) (possibly empty on last iter)
        cp_wait1();        // K(t+1) arrived (V(t+1) still in flight)
        __syncthreads();   // Kbuf visible -> loop invariant restored
    }

    // ================= epilogue: O / l =================
    const float inv0 = 1.0f / l0;
    const float inv1 = 1.0f / l1;
    float* Og = Out + base + (size_t)qt * BR_ * DIM_;
    const int r0 = warp * 16 + g;
    const int r1 = r0 + 8;
    #pragma unroll
    for (int n = 0; n < 16; n++) {
        float2 v0 = make_float2(Oa[n][0] * inv0, Oa[n][1] * inv0);
        float2 v1 = make_float2(Oa[n][2] * inv1, Oa[n][3] * inv1);
        *reinterpret_cast<float2*>(Og + (size_t)r0 * DIM_ + n * 8 + 2 * q4) = v0;
        *reinterpret_cast<float2*>(Og + (size_t)r1 * DIM_ + n * 8 + 2 * q4) = v1;
    }
}

extern "C" void kernel_launch(void* const* d_in, const int* in_sizes, int n_in,
                              void* d_out, int out_size) {
    const float* Q = (const float*)d_in[0];
    const float* K = (const float*)d_in[1];
    const float* V = (const float*)d_in[2];
    float* O = (float*)d_out;

    const size_t smem_bytes =
        (size_t)(BR_ * QSTRIDE + BC_ * KSTRIDE + BC_ * VSTRIDE) * sizeof(float); // 204800 B
    cudaFuncSetAttribute(fa_tf32_kernel, cudaFuncAttributeMaxDynamicSharedMemorySize,
                         (int)smem_bytes);

    dim3 grid(NSEQ_ / BR_, BH_);  // (32, 64): same-bh CTAs adjacent -> K/V L2 reuse
    fa_tf32_kernel<<<grid, NTHREADS, smem_bytes>>>(Q, K, V, O);
}